// round 17
// baseline (speedup 1.0000x reference)
#include <cuda_runtime.h>
#include <cuda_bf16.h>
#include <cstdint>

#define Bz  8
#define Nn  8192
#define Dm  256
#define Hh  4
#define Rr  64
#define HDd 64
#define Mm  (Bz*Nn)

typedef unsigned long long u64;

// ---------------- device scratch ----------------
__device__ float g_bK[Dm];
__device__ float g_xv[(size_t)Mm*Dm];                 // fp32 xv (exact gate term)
__device__ __nv_bfloat16 g_eb  [(size_t)Mm*Dm];       // bf16 raw exp(attn)
__device__ float g_rs[(size_t)Mm*Hh];                 // fp32 rowsum of e per (n,h)
__device__ float g_pool[Bz*Hh*Rr*HDd];                // fp32 P0 accumulator
__device__ __nv_bfloat16 g_poolb[Bz*Hh*Rr*HDd];       // bf16 P0/S
__device__ float g_S [Bz*Hh*Rr];
__device__ __nv_bfloat16 g_Wh[2][Dm*Dm];              // bf16 hi image of W ([k][n])
__device__ __nv_bfloat16 g_Wl[2][Dm*Dm];              // bf16 lo image (used by gemm0 only)

// ---------------- helpers ----------------
__device__ __forceinline__ void cpa16(uint32_t d, const void* s) {
    asm volatile("cp.async.cg.shared.global [%0], [%1], 16;" :: "r"(d), "l"(s));
}
#define CPCOMMIT() asm volatile("cp.async.commit_group;")
#define CPWAIT0()  asm volatile("cp.async.wait_group 0;")

__device__ __forceinline__ void ldsm4(uint32_t* r, uint32_t a) {
    asm volatile("ldmatrix.sync.aligned.m8n8.x4.shared.b16 {%0,%1,%2,%3}, [%4];"
        : "=r"(r[0]), "=r"(r[1]), "=r"(r[2]), "=r"(r[3]) : "r"(a));
}
__device__ __forceinline__ void ldsm4t(uint32_t* r, uint32_t a) {
    asm volatile("ldmatrix.sync.aligned.m8n8.x4.trans.shared.b16 {%0,%1,%2,%3}, [%4];"
        : "=r"(r[0]), "=r"(r[1]), "=r"(r[2]), "=r"(r[3]) : "r"(a));
}
__device__ __forceinline__ void hmma(float* c, const uint32_t* a, uint32_t b0, uint32_t b1) {
    asm volatile("mma.sync.aligned.m16n8k16.row.col.f32.bf16.bf16.f32 "
        "{%0,%1,%2,%3}, {%4,%5,%6,%7}, {%8,%9}, {%0,%1,%2,%3};"
        : "+f"(c[0]), "+f"(c[1]), "+f"(c[2]), "+f"(c[3])
        : "r"(a[0]), "r"(a[1]), "r"(a[2]), "r"(a[3]), "r"(b0), "r"(b1));
}
__device__ __forceinline__ uint2 f4_to_bf16x4(float4 v) {
    uint32_t a, b;
    asm("cvt.rn.bf16x2.f32 %0, %1, %2;" : "=r"(a) : "f"(v.y), "f"(v.x));
    asm("cvt.rn.bf16x2.f32 %0, %1, %2;" : "=r"(b) : "f"(v.w), "f"(v.z));
    return make_uint2(a, b);
}

// ---------------- fused init ----------------
__global__ void kinit(const float* __restrict__ Wq, const float* __restrict__ bq,
                      const float* __restrict__ K, const float* __restrict__ Wv) {
    int bid = blockIdx.x;
    if (bid < 512) {
        int i = bid*256 + threadIdx.x;
        if (i < Bz*Hh*Rr*HDd) g_pool[i] = 0.f;
        if (i < Bz*Hh*Rr)     g_S[i]   = 0.f;
    } else if (bid < 512 + Dm + 1) {
        int col = threadIdx.x;
        int h = col >> 6, r = col & 63;
        const float* Krow = K + r*Dm + h*HDd;
        if (bid - 512 < Dm) {
            int c = bid - 512;
            const float* wq = Wq + c*Dm + h*HDd;
            float s = 0.f;
            #pragma unroll 16
            for (int d = 0; d < HDd; d++) s = fmaf(wq[d], Krow[d], s);
            s *= 0.125f;
            __nv_bfloat16 hi = __float2bfloat16(s);
            g_Wh[1][c*Dm + col] = hi;
            g_Wl[1][c*Dm + col] = __float2bfloat16(s - __bfloat162float(hi));
        } else {
            float s = 0.f;
            #pragma unroll 16
            for (int d = 0; d < HDd; d++) s = fmaf(bq[h*HDd + d], Krow[d], s);
            g_bK[col] = 0.125f * s;
        }
    } else {
        int k = bid - (512 + Dm + 1), n = threadIdx.x;
        float wv = Wv[(size_t)k*Dm + n];
        __nv_bfloat16 hi = __float2bfloat16(wv);
        g_Wh[0][k*Dm + n] = hi;
        g_Wl[0][k*Dm + n] = __float2bfloat16(wv - __bfloat162float(hi));
    }
}

// ---------------- HMMA GEMM: C[128,128] per CTA, K=256 in 8 chunks of 32 ----------
// grid (2 nh, Mm/128, 2 gemm): nh fastest -> A rows shared by adjacent CTAs (L2 reuse)
#define KC     32
#define ABUF(s) ((s)*20480)
#define A_LOO   10240
#define BBUF(s) (40960 + (s)*17408)
#define B_LOO   8704
#define SMEM_MMA 75776

__global__ void __launch_bounds__(256, 2)
kgemm_mma(const float* __restrict__ X, const float* __restrict__ Z,
          const float* __restrict__ bias) {
    extern __shared__ char sm[];
    uint32_t smb = (uint32_t)__cvta_generic_to_shared(sm);
    const int t = threadIdx.x, w = t >> 5, lane = t & 31;
    const int m0 = blockIdx.y*128, nh = blockIdx.x;
    const int gemm = blockIdx.z;
    const float* A = gemm ? Z : X;
    const __nv_bfloat16* Wh = g_Wh[gemm];
    const __nv_bfloat16* Wl = g_Wl[gemm];
    const float* bp = gemm ? g_bK : bias;
    const int wm = (w >> 1)*32, wn = (w & 1)*64;

    float acc[2][8][4];
    #pragma unroll
    for (int i = 0; i < 2; i++)
        #pragma unroll
        for (int j = 0; j < 8; j++)
            #pragma unroll
            for (int q = 0; q < 4; q++) acc[i][j][q] = 0.f;

#define STG_B(c, s)                                                           \
    {                                                                         \
        const __nv_bfloat16* srcH = Wh + (size_t)((c)*KC)*Dm + nh*128;        \
        const __nv_bfloat16* srcL = Wl + (size_t)((c)*KC)*Dm + nh*128;        \
        _Pragma("unroll")                                                     \
        for (int p = 0; p < 2; p++) {                                         \
            int idx = t + p*256;                                              \
            int row = idx >> 4, seg = idx & 15;                               \
            uint32_t d = smb + BBUF(s) + (uint32_t)(row*272 + seg*16);        \
            cpa16(d, srcH + (size_t)row*Dm + seg*8);                          \
            if (gemm == 0)                                                    \
                cpa16(d + B_LOO, srcL + (size_t)row*Dm + seg*8);              \
        }                                                                     \
        CPCOMMIT();                                                           \
    }
#define STG_A(c, s)                                                           \
    {                                                                         \
        int row = t >> 1, half = t & 1;                                       \
        const float4* ar = (const float4*)(A + (size_t)(m0 + row)*Dm + (c)*KC + half*16); \
        float4 vv[4];                                                         \
        _Pragma("unroll")                                                     \
        for (int j4 = 0; j4 < 4; j4++) vv[j4] = ar[j4];                       \
        char* wbH = sm + ABUF(s) + row*80 + half*32;                          \
        char* wbL = wbH + A_LOO;                                              \
        uint32_t hr[8], lr[8];                                                \
        _Pragma("unroll")                                                     \
        for (int j4 = 0; j4 < 4; j4++) {                                      \
            float4 v = vv[j4];                                                \
            asm("cvt.rn.bf16x2.f32 %0, %1, %2;" : "=r"(hr[j4*2])   : "f"(v.y), "f"(v.x)); \
            asm("cvt.rn.bf16x2.f32 %0, %1, %2;" : "=r"(hr[j4*2+1]) : "f"(v.w), "f"(v.z)); \
            if (gemm == 0) {                                                  \
                float l0 = v.x - __uint_as_float(hr[j4*2] << 16);             \
                float l1 = v.y - __uint_as_float(hr[j4*2] & 0xffff0000u);     \
                float l2 = v.z - __uint_as_float(hr[j4*2+1] << 16);           \
                float l3 = v.w - __uint_as_float(hr[j4*2+1] & 0xffff0000u);   \
                asm("cvt.rn.bf16x2.f32 %0, %1, %2;" : "=r"(lr[j4*2])   : "f"(l1), "f"(l0)); \
                asm("cvt.rn.bf16x2.f32 %0, %1, %2;" : "=r"(lr[j4*2+1]) : "f"(l3), "f"(l2)); \
            }                                                                 \
        }                                                                     \
        *(uint4*)(wbH +  0) = make_uint4(hr[0], hr[1], hr[2], hr[3]);         \
        *(uint4*)(wbH + 16) = make_uint4(hr[4], hr[5], hr[6], hr[7]);         \
        if (gemm == 0) {                                                      \
            *(uint4*)(wbL +  0) = make_uint4(lr[0], lr[1], lr[2], lr[3]);     \
            *(uint4*)(wbL + 16) = make_uint4(lr[4], lr[5], lr[6], lr[7]);     \
        }                                                                     \
    }

    STG_B(0, 0);
    STG_A(0, 0);

    for (int c = 0; c < 8; c++) {
        int s = c & 1;
        CPWAIT0();
        __syncthreads();
        if (c < 7) {
            STG_B(c + 1, s ^ 1);
            STG_A(c + 1, s ^ 1);
        }
        uint32_t aoff = smb + ABUF(s) + (uint32_t)((wm + (lane & 15))*80) + (lane >> 4)*16;
        uint32_t boff = smb + BBUF(s) + (uint32_t)((lane & 15)*272) + (uint32_t)((wn + (lane >> 4)*8)*2);
        if (gemm == 0) {
            #pragma unroll
            for (int ks = 0; ks < 2; ks++) {
                uint32_t ah[2][4], al[2][4];
                uint32_t ab = aoff + ks*32;
                ldsm4(ah[0], ab);
                ldsm4(ah[1], ab + 16*80);
                ldsm4(al[0], ab + A_LOO);
                ldsm4(al[1], ab + A_LOO + 16*80);
                uint32_t bb = boff + ks*16*272;
                #pragma unroll
                for (int nq = 0; nq < 4; nq++) {
                    uint32_t bh[4], bl[4];
                    ldsm4t(bh, bb + nq*32);
                    ldsm4t(bl, bb + nq*32 + B_LOO);
                    #pragma unroll
                    for (int mt = 0; mt < 2; mt++) {
                        #pragma unroll
                        for (int sub = 0; sub < 2; sub++) {
                            float* cc = acc[mt][nq*2 + sub];
                            hmma(cc, ah[mt], bh[sub*2], bh[sub*2+1]);
                            hmma(cc, al[mt], bh[sub*2], bh[sub*2+1]);
                            hmma(cc, ah[mt], bl[sub*2], bl[sub*2+1]);
                        }
                    }
                }
            }
        } else {
            #pragma unroll
            for (int ks = 0; ks < 2; ks++) {
                uint32_t ah[2][4];
                uint32_t ab = aoff + ks*32;
                ldsm4(ah[0], ab);
                ldsm4(ah[1], ab + 16*80);
                uint32_t bb = boff + ks*16*272;
                #pragma unroll
                for (int nq = 0; nq < 4; nq++) {
                    uint32_t bh[4];
                    ldsm4t(bh, bb + nq*32);
                    #pragma unroll
                    for (int mt = 0; mt < 2; mt++) {
                        #pragma unroll
                        for (int sub = 0; sub < 2; sub++) {
                            float* cc = acc[mt][nq*2 + sub];
                            hmma(cc, ah[mt], bh[sub*2], bh[sub*2+1]);
                        }
                    }
                }
            }
        }
    }

    // ---- register-direct epilogue ----
    const float* bp2 = bp + nh*128;
    const int rl = lane >> 2, cq = (lane & 3)*2;
    if (gemm == 0) {
        #pragma unroll
        for (int mt = 0; mt < 2; mt++)
            #pragma unroll
            for (int j = 0; j < 8; j++) {
                int cl = wn + j*8 + cq;
                float b0 = bp2[cl], b1 = bp2[cl+1];
                int r = m0 + wm + mt*16 + rl;
                float2 o0 = {acc[mt][j][0] + b0, acc[mt][j][1] + b1};
                float2 o1 = {acc[mt][j][2] + b0, acc[mt][j][3] + b1};
                *(float2*)(g_xv + (size_t)r*Dm + nh*128 + cl)     = o0;
                *(float2*)(g_xv + (size_t)(r+8)*Dm + nh*128 + cl) = o1;
            }
    } else {
        float ps[2][2] = {{0.f,0.f},{0.f,0.f}};
        #pragma unroll
        for (int mt = 0; mt < 2; mt++)
            #pragma unroll
            for (int j = 0; j < 8; j++) {
                int cl = wn + j*8 + cq;
                float b0 = bp2[cl], b1 = bp2[cl+1];
                int r = m0 + wm + mt*16 + rl;
                float e00 = __expf(acc[mt][j][0] + b0);
                float e01 = __expf(acc[mt][j][1] + b1);
                float e10 = __expf(acc[mt][j][2] + b0);
                float e11 = __expf(acc[mt][j][3] + b1);
                ps[mt][0] += e00 + e01;
                ps[mt][1] += e10 + e11;
                uint32_t p0, p1;
                asm("cvt.rn.bf16x2.f32 %0, %1, %2;" : "=r"(p0) : "f"(e01), "f"(e00));
                asm("cvt.rn.bf16x2.f32 %0, %1, %2;" : "=r"(p1) : "f"(e11), "f"(e10));
                *(uint32_t*)(g_eb + (size_t)r*Dm + nh*128 + cl)     = p0;
                *(uint32_t*)(g_eb + (size_t)(r+8)*Dm + nh*128 + cl) = p1;
            }
        int head = nh*2 + (w & 1);
        #pragma unroll
        for (int mt = 0; mt < 2; mt++)
            #pragma unroll
            for (int rr = 0; rr < 2; rr++) {
                float s = ps[mt][rr];
                s += __shfl_xor_sync(0xffffffffu, s, 1);
                s += __shfl_xor_sync(0xffffffffu, s, 2);
                if ((lane & 3) == 0) {
                    int r = m0 + wm + mt*16 + rl + rr*8;
                    g_rs[(size_t)r*Hh + head] = s;
                }
            }
    }
}

// ---------------- kpool ----------------
#define ONESB 0x3F803F80u
__global__ void __launch_bounds__(256, 4) kpool() {
    __shared__ char smE[2][64*144];
    __shared__ char smX[2][64*144];
    uint32_t sE[2] = {(uint32_t)__cvta_generic_to_shared(smE[0]),
                      (uint32_t)__cvta_generic_to_shared(smE[1])};
    uint32_t sX[2] = {(uint32_t)__cvta_generic_to_shared(smX[0]),
                      (uint32_t)__cvta_generic_to_shared(smX[1])};
    const int t = threadIdx.x, w = t >> 5, lane = t & 31;
    const int ch = blockIdx.x, h = blockIdx.y, b = blockIdx.z;
    const int r_base = (w & 3)*16, d_base = (w >> 2)*32;
    float acc[4][4];
    #pragma unroll
    for (int i = 0; i < 4; i++)
        #pragma unroll
        for (int q = 0; q < 4; q++) acc[i][q] = 0.f;
    float acc2[4] = {0.f, 0.f, 0.f, 0.f};

#define STG_EX(tl, s)                                                         \
    {                                                                         \
        int n0 = ch*512 + (tl)*64;                                            \
        size_t gbase = ((size_t)(b*Nn + n0))*Dm + h*64;                       \
        _Pragma("unroll")                                                     \
        for (int p = 0; p < 2; p++) {                                         \
            int c = t + p*256;                                                \
            int row = c >> 3, off = c & 7;                                    \
            cpa16(sE[s] + row*144 + off*16, g_eb + gbase + (size_t)row*Dm + off*8); \
        }                                                                     \
        CPCOMMIT();                                                           \
        _Pragma("unroll")                                                     \
        for (int p = 0; p < 4; p++) {                                         \
            int c = t + p*256;                                                \
            int row = c >> 4, col4 = c & 15;                                  \
            float4 v = *(const float4*)(g_xv + gbase + (size_t)row*Dm + col4*4); \
            float inv = __fdividef(1.f, g_rs[((size_t)(b*Nn + n0 + row))*Hh + h]); \
            float4 sv = {v.x*inv, v.y*inv, v.z*inv, v.w*inv};                 \
            *(uint2*)(smX[s] + row*144 + col4*8) = f4_to_bf16x4(sv);          \
        }                                                                     \
    }

    STG_EX(0, 0);

    for (int tile = 0; tile < 8; tile++) {
        int s = tile & 1;
        CPWAIT0();
        __syncthreads();
        if (tile < 7) STG_EX(tile + 1, s ^ 1);

        uint32_t aoff = sE[s] + (uint32_t)((((lane >> 4) << 3) + (lane & 7))*144)
                      + (uint32_t)((r_base + (((lane >> 3) & 1) << 3))*2);
        uint32_t boff = sX[s] + (uint32_t)((lane & 15)*144) + (uint32_t)((d_base + (lane >> 4)*8)*2);
        #pragma unroll
        for (int ks = 0; ks < 4; ks++) {
            uint32_t a[4];
            ldsm4t(a, aoff + ks*16*144);
            if (w < 4) hmma(acc2, a, ONESB, ONESB);
            #pragma unroll
            for (int dq = 0; dq < 2; dq++) {
                uint32_t bf[4];
                ldsm4t(bf, boff + ks*16*144 + dq*32);
                hmma(acc[dq*2],   a, bf[0], bf[1]);
                hmma(acc[dq*2+1], a, bf[2], bf[3]);
            }
        }
        __syncthreads();
    }
    float* pp = g_pool + ((size_t)(b*Hh + h)*Rr)*HDd;
    #pragma unroll
    for (int i = 0; i < 4; i++) {
        int r = r_base + (lane >> 2);
        int d = d_base + i*8 + (lane & 3)*2;
        atomicAdd(&pp[r*HDd + d],       acc[i][0]);
        atomicAdd(&pp[r*HDd + d + 1],   acc[i][1]);
        atomicAdd(&pp[(r+8)*HDd + d],   acc[i][2]);
        atomicAdd(&pp[(r+8)*HDd + d+1], acc[i][3]);
    }
    if (w < 4 && (lane & 3) == 0) {
        int r = r_base + (lane >> 2);
        atomicAdd(&g_S[(b*Hh + h)*Rr + r],     acc2[0]);
        atomicAdd(&g_S[(b*Hh + h)*Rr + r + 8], acc2[2]);
    }
}

// ---------------- kfin: poolb = bf16(P0/S), properly parallel ----------------
__global__ void kfin() {
    int idx = blockIdx.x*256 + threadIdx.x;      // 16384 threads, 8 elems each
    int row = idx >> 3, seg = idx & 7;
    float inv = 1.f / g_S[row];
    const float4* p = (const float4*)(g_pool + (size_t)row*HDd + seg*8);
    float4 v0 = p[0], v1 = p[1];
    v0.x *= inv; v0.y *= inv; v0.z *= inv; v0.w *= inv;
    v1.x *= inv; v1.y *= inv; v1.z *= inv; v1.w *= inv;
    uint2* q = (uint2*)(g_poolb + (size_t)row*HDd + seg*8);
    q[0] = f4_to_bf16x4(v0);
    q[1] = f4_to_bf16x4(v1);
}

// ---------------- kout: 32-row tiles, 4 CTA/SM, P staged via cp.async ----------------
#define KO_E  0                  // 32 rows x 528B = 16896
#define KO_P  16896              // 256 rows x 144B = 36864
#define SMEM_KOUT 53760
__global__ void __launch_bounds__(256, 4)
kout(const float* __restrict__ alpha, const float* __restrict__ beta,
     float* __restrict__ out) {
    extern __shared__ char sm[];
    uint32_t smb = (uint32_t)__cvta_generic_to_shared(sm);
    const int t = threadIdx.x, w = t >> 5, lane = t & 31;
    const int b = blockIdx.x >> 8;
    const int n0 = (blockIdx.x & 255)*32;
    const int hw = w & 3, m_base = (w >> 2)*16;
    size_t gbase = ((size_t)(b*Nn + n0))*Dm;

    // stage E (32 rows) + P (bf16, L2-resident) via cp.async
    #pragma unroll
    for (int p = 0; p < 4; p++) {
        int c = t + p*256;
        int row = c >> 5, off = c & 31;
        cpa16(smb + KO_E + row*528 + off*16, g_eb + gbase + (size_t)row*Dm + off*8);
    }
    const __nv_bfloat16* pbase = g_poolb + (size_t)b*(Hh*Rr*HDd);
    #pragma unroll
    for (int p = 0; p < 8; p++) {
        int c = t + p*256;
        int prow = c >> 3, poff = c & 7;
        cpa16(smb + KO_P + prow*144 + poff*16, pbase + prow*64 + poff*8);
    }
    CPCOMMIT();
    CPWAIT0();
    __syncthreads();

    float sa = 1.f / (1.f + __expf(-alpha[hw]));
    float sb = 1.f / (1.f + __expf(-beta[hw]));
    uint32_t boff = smb + KO_P + (uint32_t)(hw*9216)
                  + (uint32_t)((lane & 15)*144) + (uint32_t)((lane >> 4)*16);
    const int colb = hw*64 + (lane & 3)*2;

    float acc[8][4];
    #pragma unroll
    for (int j = 0; j < 8; j++)
        #pragma unroll
        for (int q = 0; q < 4; q++) acc[j][q] = 0.f;

    uint32_t aoff = smb + KO_E + (uint32_t)((m_base + (lane & 15))*528)
                  + (uint32_t)(hw*128) + (lane >> 4)*16;
    #pragma unroll
    for (int ks = 0; ks < 4; ks++) {
        uint32_t a[4];
        ldsm4(a, aoff + ks*32);
        #pragma unroll
        for (int dq = 0; dq < 4; dq++) {
            uint32_t bf[4];
            ldsm4t(bf, boff + ks*16*144 + dq*32);
            hmma(acc[dq*2],   a, bf[0], bf[1]);
            hmma(acc[dq*2+1], a, bf[2], bf[3]);
        }
    }

    int row = m_base + (lane >> 2);
    const float* xvp0 = g_xv + gbase + (size_t)row*Dm + colb;
    float* op0 = out + gbase + (size_t)row*Dm + colb;
    {
        float2 xv0[8];
        #pragma unroll
        for (int j = 0; j < 8; j++) xv0[j] = *(const float2*)(xvp0 + j*8);
        #pragma unroll
        for (int j = 0; j < 8; j++) {
            float2 o = {fmaf(sa, xv0[j].x, sb*acc[j][0]),
                        fmaf(sa, xv0[j].y, sb*acc[j][1])};
            *(float2*)(op0 + j*8) = o;
        }
    }
    {
        const float* xvp1 = xvp0 + 8*Dm;
        float* op1 = op0 + 8*Dm;
        float2 xv1[8];
        #pragma unroll
        for (int j = 0; j < 8; j++) xv1[j] = *(const float2*)(xvp1 + j*8);
        #pragma unroll
        for (int j = 0; j < 8; j++) {
            float2 o = {fmaf(sa, xv1[j].x, sb*acc[j][2]),
                        fmaf(sa, xv1[j].y, sb*acc[j][3])};
            *(float2*)(op1 + j*8) = o;
        }
    }
}

extern "C" void kernel_launch(void* const* d_in, const int* in_sizes, int n_in,
                              void* d_out, int out_size) {
    const float* x     = (const float*)d_in[0];
    const float* z     = (const float*)d_in[1];
    const float* Wq    = (const float*)d_in[2];
    const float* bq    = (const float*)d_in[3];
    const float* K     = (const float*)d_in[4];
    const float* Wv    = (const float*)d_in[5];
    const float* bv    = (const float*)d_in[6];
    const float* alpha = (const float*)d_in[7];
    const float* beta  = (const float*)d_in[8];
    float* out = (float*)d_out;

    cudaFuncSetAttribute(kgemm_mma, cudaFuncAttributeMaxDynamicSharedMemorySize, SMEM_MMA);
    cudaFuncSetAttribute(kout,      cudaFuncAttributeMaxDynamicSharedMemorySize, SMEM_KOUT);

    kinit<<<512 + Dm + 1 + Dm, 256>>>(Wq, bq, K, Wv);
    kgemm_mma<<<dim3(2, Mm/128, 2), 256, SMEM_MMA>>>(x, z, bv);  // nh fastest -> A L2 reuse
    kpool<<<dim3(16, Hh, Bz), 256>>>();
    kfin<<<64, 256>>>();
    kout<<<Mm/32, 256, SMEM_KOUT>>>(alpha, beta, out);
}